// round 5
// baseline (speedup 1.0000x reference)
#include <cuda_runtime.h>
#include <cstdint>
#include <cstddef>

// ============================================================================
// Problem constants
// ============================================================================
#define GROUPS 8
#define TOKENS 16384
#define IN_F   1024
#define OUT_F  1024

// Tiling: CTA 128x128x32, 4 warps, warp tile 64x64, mma.sync m16n8k8 tf32
#define BM 128
#define BN 128
#define BK 32
#define NCHUNKS (IN_F / BK)          // 32
#define STAGES 3
#define THREADS 128

// SMEM (floats), padded for conflict-free fragment gathers
#define A_ROW 36                     // 32 + 4 pad  -> lane banks 4g+tig
#define B_ROW 136                    // 128 + 8 pad -> lane banks 8tig+g
#define A_BYTES (BM * A_ROW * 4)     // 18432
#define B_BYTES (BK * B_ROW * 4)     // 17408
#define STAGE_BYTES (A_BYTES + B_BYTES)      // 35840
#define SMEM_TOTAL  (STAGES * STAGE_BYTES)   // 107520

#define M_TILES (TOKENS / BM)        // 128
#define N_TILES (OUT_F / BN)         // 8

// ============================================================================
// PTX helpers (sm_80+ features only — plain sm_100 target rejects tcgen05)
// ============================================================================
__device__ __forceinline__ uint32_t smem_u32(const void* p) {
    uint32_t a;
    asm("{ .reg .u64 t; cvta.to.shared.u64 t, %1; cvt.u32.u64 %0, t; }" : "=r"(a) : "l"(p));
    return a;
}

__device__ __forceinline__ uint32_t f2tf(float x) {
    uint32_t r;
    asm("cvt.rna.tf32.f32 %0, %1;" : "=r"(r) : "f"(x));
    return r;
}

#define CP_ASYNC16(dst_u32, src_ptr) \
    asm volatile("cp.async.cg.shared.global [%0], [%1], 16;" \
                 :: "r"(dst_u32), "l"(src_ptr) : "memory")
#define CP_COMMIT() asm volatile("cp.async.commit_group;" ::: "memory")
#define CP_WAIT1()  asm volatile("cp.async.wait_group 1;" ::: "memory")
#define CP_WAIT0()  asm volatile("cp.async.wait_group 0;" ::: "memory")

// D = A*B + D   (m16n8k8, tf32, row.col)
#define MMA_TF32(c0,c1,c2,c3, a0,a1,a2,a3, b0,b1)                              \
    asm volatile("mma.sync.aligned.m16n8k8.row.col.f32.tf32.tf32.f32 "         \
                 "{%0,%1,%2,%3}, {%4,%5,%6,%7}, {%8,%9}, {%0,%1,%2,%3};"       \
                 : "+f"(c0), "+f"(c1), "+f"(c2), "+f"(c3)                      \
                 : "r"(a0), "r"(a1), "r"(a2), "r"(a3), "r"(b0), "r"(b1))

// ============================================================================
// GEMM kernel: grouped linear, tf32 mma.sync, 3-stage cp.async pipeline
// ============================================================================
__global__ void __launch_bounds__(THREADS) grouped_gemm_kernel(
    const float* __restrict__ A,        // [TOKENS][IN_F]
    const float* __restrict__ W,        // [GROUPS][IN_F][OUT_F]
    const void* __restrict__ offsets_raw,   // [GROUPS] cumulative ends (int32 OR int64)
    float* __restrict__ out)            // [TOKENS][OUT_F]
{
    extern __shared__ float sm[];
    const uint32_t sm_base = smem_u32(sm);

    const int tid  = threadIdx.x;
    const int wid  = tid >> 5;
    const int lane = tid & 31;
    const int g8   = lane >> 2;     // groupID (0..7)
    const int tig  = lane & 3;      // thread-in-group (0..3)

    // m-major CTA order: 8 n-tiles of the same m-tile adjacent -> A L2 reuse
    const int m_tile = blockIdx.x >> 3;
    const int n_tile = blockIdx.x & 7;
    const int row0   = m_tile * BM;
    const int n0     = n_tile * BN;

    // ---- expert group of this M-tile -------------------------------------
    // Dtype-robust: JAX under default config materializes "int64" as int32.
    // Sniff with 32-bit loads only (always within the 32-byte minimum buffer):
    // int64 layout -> offs32[1] is the high word of offsets[0] == 0;
    // int32 layout -> offs32[1] == offsets[1] (4096) != 0.
    const int* offs32 = (const int*)offsets_raw;
    const bool is64 = (offs32[1] == 0);
    int g = 0;
    if (is64) {
        const long long* o64 = (const long long*)offsets_raw;
#pragma unroll
        for (int i = 0; i < GROUPS; i++)
            if (o64[i] <= (long long)row0) g = i + 1;
    } else {
#pragma unroll
        for (int i = 0; i < GROUPS; i++)
            if (offs32[i] <= row0) g = i + 1;
    }
    if (g > GROUPS - 1) g = GROUPS - 1;   // never index past W

    const float* Wg = W + (size_t)g * IN_F * OUT_F;

    // warp position: 2x2 warps, each 64x64
    const int mW = (wid >> 1) * 64;
    const int nW = (wid & 1) * 64;

    // ---- cp.async source/dest precompute ---------------------------------
    uint32_t a_dst[8], b_dst[8];
    const float* a_src[8];
    const float* b_src[8];
#pragma unroll
    for (int t = 0; t < 8; t++) {
        int lin = tid + t * THREADS;
        int am = lin >> 3, aj = lin & 7;
        a_dst[t] = sm_base + (uint32_t)(am * A_ROW + aj * 4) * 4u;
        a_src[t] = A + (size_t)(row0 + am) * IN_F + aj * 4;
        int bk = lin >> 5, bj = lin & 31;
        b_dst[t] = sm_base + (uint32_t)A_BYTES + (uint32_t)(bk * B_ROW + bj * 4) * 4u;
        b_src[t] = Wg + (size_t)bk * OUT_F + n0 + bj * 4;
    }

    // C accumulators: 4 m-tiles x 8 n-tiles x 4 regs
    float c[4][8][4];
#pragma unroll
    for (int mt = 0; mt < 4; mt++)
#pragma unroll
        for (int nt = 0; nt < 8; nt++)
#pragma unroll
            for (int q = 0; q < 4; q++) c[mt][nt][q] = 0.f;

    // ---- pipeline prologue: issue chunks 0,1 -----------------------------
#pragma unroll
    for (int pc = 0; pc < 2; pc++) {
        uint32_t so = (uint32_t)(pc * STAGE_BYTES);
#pragma unroll
        for (int t = 0; t < 8; t++) {
            CP_ASYNC16(a_dst[t] + so, a_src[t] + (size_t)pc * BK);
            CP_ASYNC16(b_dst[t] + so, b_src[t] + (size_t)pc * BK * OUT_F);
        }
        CP_COMMIT();
    }

    // ---- main loop -------------------------------------------------------
    for (int cidx = 0; cidx < NCHUNKS; cidx++) {
        if (cidx == NCHUNKS - 1) { CP_WAIT0(); } else { CP_WAIT1(); }
        __syncthreads();

        // prefetch chunk cidx+2 into the stage freed at iteration cidx-1
        if (cidx + 2 < NCHUNKS) {
            int pc = cidx + 2;
            uint32_t so = (uint32_t)((pc % STAGES) * STAGE_BYTES);
#pragma unroll
            for (int t = 0; t < 8; t++) {
                CP_ASYNC16(a_dst[t] + so, a_src[t] + (size_t)pc * BK);
                CP_ASYNC16(b_dst[t] + so, b_src[t] + (size_t)pc * BK * OUT_F);
            }
            CP_COMMIT();
        }

        // compute on stage cidx%3
        const float* As = sm + (size_t)(cidx % STAGES) * (STAGE_BYTES / 4);
        const float* Bs = As + A_BYTES / 4;

#pragma unroll
        for (int ks = 0; ks < 4; ks++) {           // 4 k-steps of 8
            const int k0 = ks * 8;

            uint32_t af[4][4];
#pragma unroll
            for (int mt = 0; mt < 4; mt++) {
                const int r = mW + mt * 16 + g8;
                af[mt][0] = f2tf(As[(r    ) * A_ROW + k0 + tig    ]);
                af[mt][1] = f2tf(As[(r + 8) * A_ROW + k0 + tig    ]);
                af[mt][2] = f2tf(As[(r    ) * A_ROW + k0 + tig + 4]);
                af[mt][3] = f2tf(As[(r + 8) * A_ROW + k0 + tig + 4]);
            }

            uint32_t bf[8][2];
#pragma unroll
            for (int nt = 0; nt < 8; nt++) {
                const int col = nW + nt * 8 + g8;
                bf[nt][0] = f2tf(Bs[(k0 + tig    ) * B_ROW + col]);
                bf[nt][1] = f2tf(Bs[(k0 + tig + 4) * B_ROW + col]);
            }

#pragma unroll
            for (int mt = 0; mt < 4; mt++)
#pragma unroll
                for (int nt = 0; nt < 8; nt++)
                    MMA_TF32(c[mt][nt][0], c[mt][nt][1], c[mt][nt][2], c[mt][nt][3],
                             af[mt][0], af[mt][1], af[mt][2], af[mt][3],
                             bf[nt][0], bf[nt][1]);
        }
    }

    // ---- epilogue: c mapping (g8 row, 2*tig col) -------------------------
#pragma unroll
    for (int mt = 0; mt < 4; mt++) {
        const int r = row0 + mW + mt * 16 + g8;
#pragma unroll
        for (int nt = 0; nt < 8; nt++) {
            const int colb = n0 + nW + nt * 8 + 2 * tig;
            float2 v0 = make_float2(c[mt][nt][0], c[mt][nt][1]);
            float2 v1 = make_float2(c[mt][nt][2], c[mt][nt][3]);
            *reinterpret_cast<float2*>(out + (size_t)r * OUT_F + colb)       = v0;
            *reinterpret_cast<float2*>(out + (size_t)(r + 8) * OUT_F + colb) = v1;
        }
    }
}

// ============================================================================
// Host side — no static guards; bind pointers by element count, not order.
// ============================================================================
extern "C" void kernel_launch(void* const* d_in, const int* in_sizes, int n_in,
                              void* d_out, int out_size) {
    const float* hidden  = nullptr;
    const float* weight  = nullptr;
    const void*  offsets = nullptr;

    for (int i = 0; i < n_in; i++) {
        if (in_sizes[i] == TOKENS * IN_F)                hidden  = (const float*)d_in[i];
        else if (in_sizes[i] == GROUPS * IN_F * OUT_F)   weight  = (const float*)d_in[i];
        else                                             offsets = d_in[i];
    }
    float* out = (float*)d_out;

    cudaFuncSetAttribute(grouped_gemm_kernel,
                         cudaFuncAttributeMaxDynamicSharedMemorySize, SMEM_TOTAL);

    grouped_gemm_kernel<<<M_TILES * N_TILES, THREADS, SMEM_TOTAL>>>(
        hidden, weight, offsets, out);
}